// round 14
// baseline (speedup 1.0000x reference)
#include <cuda_runtime.h>
#include <cuda_fp16.h>
#include <math.h>
#include <stdint.h>

// Problem dimensions (fixed by the reference)
#define BB    4
#define SS    2048
#define DM    1024
#define HH    16
#define DK    64
#define DFF   4096
#define MROWS (BB*SS)          // 8192
#define QKVS  3072             // fused QKV row stride
#define LN_EPS 1e-5f

// ---------------------------------------------------------------------------
// Scratch (device globals; no allocations allowed)
// ---------------------------------------------------------------------------
__device__ __half g_h   [MROWS*DM];     // ln1 / ln2 output (fp16)
__device__ __half g_qkv [MROWS*QKVS];   // fused Q|K|V (fp16)
__device__ __half g_o   [MROWS*DM];     // attention output (fp16)
__device__ float  g_x1  [MROWS*DM];     // residual after attention (fp32)
__device__ __half g_ff  [MROWS*DFF];    // FFN hidden (fp16)
__device__ __half g_wqkvt[QKVS*DM];     // fused transposed weights [3072,1024]
__device__ __half g_wot [DM*DM];
__device__ __half g_w1t [DFF*DM];       // [4096,1024]
__device__ __half g_w2t [DM*DFF];       // [1024,4096]
__device__ float  g_bqkv[QKVS];         // fused bias

// ---------------------------------------------------------------------------
// Helpers
// ---------------------------------------------------------------------------
__device__ __forceinline__ uint32_t smem_u32(const void* p) {
    uint32_t a;
    asm("{ .reg .u64 t; cvta.to.shared.u64 t, %1; cvt.u32.u64 %0, t; }"
        : "=r"(a) : "l"(p));
    return a;
}

__device__ __forceinline__ uint32_t pack_h2(float lo, float hi) {
    __half2 h = __floats2half2_rn(lo, hi);
    return *reinterpret_cast<uint32_t*>(&h);
}

__device__ __forceinline__ float ex2(float x) {        // 2^x, MUFU.EX2
    float y;
    asm("ex2.approx.f32 %0, %1;" : "=f"(y) : "f"(x));
    return y;
}

#define CP_ASYNC16(dst, src) \
    asm volatile("cp.async.cg.shared.global [%0], [%1], 16;" :: "r"(dst), "l"(src))
#define CP_COMMIT()  asm volatile("cp.async.commit_group;" ::: "memory")
#define CP_WAIT(n)   asm volatile("cp.async.wait_group %0;" :: "n"(n) : "memory")

// m16n8k16 fp16 mma, fp32 accumulate
#define MMA_F16(d, a, b0, b1) \
    asm volatile("mma.sync.aligned.m16n8k16.row.col.f32.f16.f16.f32 " \
        "{%0,%1,%2,%3}, {%4,%5,%6,%7}, {%8,%9}, {%0,%1,%2,%3};" \
        : "+f"(d[0]), "+f"(d[1]), "+f"(d[2]), "+f"(d[3]) \
        : "r"(a[0]), "r"(a[1]), "r"(a[2]), "r"(a[3]), "r"(b0), "r"(b1))

#define LDSM_X4(r0, r1, r2, r3, addr) \
    asm volatile("ldmatrix.sync.aligned.m8n8.x4.shared.b16 {%0,%1,%2,%3}, [%4];" \
        : "=r"(r0), "=r"(r1), "=r"(r2), "=r"(r3) : "r"(addr))

#define LDSM_X4_TRANS(r0, r1, r2, r3, addr) \
    asm volatile("ldmatrix.sync.aligned.m8n8.x4.trans.shared.b16 {%0,%1,%2,%3}, [%4];" \
        : "=r"(r0), "=r"(r1), "=r"(r2), "=r"(r3) : "r"(addr))

// ---------------------------------------------------------------------------
// LayerNorm -> fp16, warp-per-row (8 rows per 256-thread block, no barriers)
// ---------------------------------------------------------------------------
__global__ __launch_bounds__(256) void ln_kernel(
    const float* __restrict__ X, const float* __restrict__ gamma,
    const float* __restrict__ beta, __half* __restrict__ out)
{
    const int t = threadIdx.x, lane = t & 31, w = t >> 5;
    const int row = blockIdx.x*8 + w;

    cudaGridDependencySynchronize();

    const float4* Xr = (const float4*)(X + (size_t)row*DM);
    float4 v[8];
    float s = 0.f, ss = 0.f;
    #pragma unroll
    for (int i = 0; i < 8; i++) {
        v[i] = Xr[lane + i*32];
        s  += v[i].x + v[i].y + v[i].z + v[i].w;
        ss += v[i].x*v[i].x + v[i].y*v[i].y + v[i].z*v[i].z + v[i].w*v[i].w;
    }
    #pragma unroll
    for (int o = 16; o > 0; o >>= 1) {
        s  += __shfl_xor_sync(0xffffffffu, s,  o);
        ss += __shfl_xor_sync(0xffffffffu, ss, o);
    }
    const float mu   = s * (1.0f / DM);
    const float var  = ss * (1.0f / DM) - mu*mu;
    const float rstd = rsqrtf(var + LN_EPS);

    const float4* G  = (const float4*)gamma;
    const float4* Bt = (const float4*)beta;
    uint2* Or = (uint2*)(out + (size_t)row*DM);
    #pragma unroll
    for (int i = 0; i < 8; i++) {
        const float4 g4 = G[lane + i*32];
        const float4 b4 = Bt[lane + i*32];
        uint2 st;
        st.x = pack_h2((v[i].x - mu)*rstd*g4.x + b4.x,
                       (v[i].y - mu)*rstd*g4.y + b4.y);
        st.y = pack_h2((v[i].z - mu)*rstd*g4.z + b4.z,
                       (v[i].w - mu)*rstd*g4.w + b4.w);
        Or[lane + i*32] = st;
    }
}

// ---------------------------------------------------------------------------
// Single prep kernel: z=0..5 -> transpose+round of Wq/Wk/Wv/Wo/W1/W2,
// bias concat folded into z=0 blocks 1024..1035. Grid (4096,1,6), block 256.
// ---------------------------------------------------------------------------
__global__ __launch_bounds__(256) void prep_kernel(
    const float* __restrict__ Wq, const float* __restrict__ Wk,
    const float* __restrict__ Wv, const float* __restrict__ Wo,
    const float* __restrict__ W1, const float* __restrict__ W2,
    __half* __restrict__ Tqkv, __half* __restrict__ To,
    __half* __restrict__ T1, __half* __restrict__ T2,
    const float* __restrict__ bq, const float* __restrict__ bk,
    const float* __restrict__ bv, float* __restrict__ bqkv)
{
    const int z = blockIdx.z;
    const float* W; __half* T; int K, N;
    switch (z) {
        case 0:  W = Wq; T = Tqkv;           K = DM;  N = DM;  break;
        case 1:  W = Wk; T = Tqkv + DM*DM;   K = DM;  N = DM;  break;
        case 2:  W = Wv; T = Tqkv + 2*DM*DM; K = DM;  N = DM;  break;
        case 3:  W = Wo; T = To;             K = DM;  N = DM;  break;
        case 4:  W = W1; T = T1;             K = DM;  N = DFF; break;
        default: W = W2; T = T2;             K = DFF; N = DM;  break;
    }
    // bias concat on z=0 blocks 1024..1035
    if (z == 0 && blockIdx.x >= 1024) {
        if (blockIdx.x < 1036) {
            const int i = (blockIdx.x - 1024)*256 + threadIdx.x;
            if (i < DM)        bqkv[i] = bq[i];
            else if (i < 2*DM) bqkv[i] = bk[i - DM];
            else               bqkv[i] = bv[i - 2*DM];
        }
        return;
    }
    const int nblk = N >> 5;
    const int bx = blockIdx.x % nblk, byk = blockIdx.x / nblk;
    if (byk >= (K >> 5)) return;

    __shared__ float tile[32][33];
    const int tx = threadIdx.x & 31, ty = threadIdx.x >> 5;
    const int n0 = bx*32, k0 = byk*32;
    #pragma unroll
    for (int i = ty; i < 32; i += 8)
        tile[i][tx] = W[(size_t)(k0 + i)*N + n0 + tx];
    __syncthreads();
    #pragma unroll
    for (int i = ty; i < 32; i += 8)
        T[(size_t)(n0 + i)*K + k0 + tx] = __float2half_rn(tile[tx][i]);
}

// ---------------------------------------------------------------------------
// fp16 mma.sync GEMM: C[M,N] = A[M,K] @ Bt[N,K]^T + bias (+relu)(+res)
// 128x128 CTA tile, BK=64, 3-stage cp.async, 256 threads (8 warps, 2x4),
// warp tile 64x32, ldmatrix x4 fragments, 2 CTAs/SM. Weight (B) tiles for
// the first two stages prefetch BEFORE the PDL dependency sync (weights are
// prep_kernel output; prep is transitively complete -- ln#1 is a plain
// launch). Stage indices via increment-wrap counters (no integer div).
// ---------------------------------------------------------------------------
#define GST    3
#define LDH    72
#define TILE_H (128*LDH)                 // halves per tile (9216)
#define STAGE_BYTES (2*TILE_H*2)         // A + B = 36864 B
#define GEMM_SMEM (GST*STAGE_BYTES)      // 110592 B

template<bool RELU, bool RES, bool HALF_OUT>
__global__ __launch_bounds__(256, 2) void mma_gemm(
    const __half* __restrict__ A, const __half* __restrict__ Bt,
    const float* __restrict__ bias, const float* __restrict__ res,
    void* __restrict__ Cv, int M, int N, int K)
{
    extern __shared__ char smc[];
    const uint32_t sm_b = smem_u32(smc);

    const int tid  = threadIdx.x;
    const int lane = tid & 31, wid = tid >> 5;
    const int wm = wid >> 2, wn = wid & 3;        // 2 x 4 warp grid
    const int gid = lane >> 2, tg = lane & 3;
    const int bx = blockIdx.x, by = blockIdx.y;

    const __half* Ab = A  + (size_t)by * 128 * K;
    const __half* Bb = Bt + (size_t)bx * 128 * K;
    const int nchunks = K >> 6;                   // K/64

    // ldmatrix per-lane offsets (bytes) within a stage's A / B tile
    const int la7    = lane & 7;
    const int colsel = ((lane >> 3) & 1) << 3;    // 0/8 (k half)
    const int rowsel = (lane >> 4) << 3;          // 0/8 (row group)
    uint32_t offA[4], offB4[2];
    {
        const int arow = la7 + ((lane >> 3) & 1) * 8;
        const int acol = (lane >> 4) * 8;
        #pragma unroll
        for (int mt = 0; mt < 4; mt++)
            offA[mt] = (uint32_t)(((wm*64 + mt*16 + arow)*LDH + acol) * 2);
        #pragma unroll
        for (int g = 0; g < 2; g++)
            offB4[g] = (uint32_t)(((wn*32 + g*16 + la7 + rowsel)*LDH + colsel) * 2);
    }

    // Stage loaders (A and B separable for PDL weight prefetch)
    auto load_A = [&](int st, int kt) {
        const uint32_t a_dst = sm_b + (uint32_t)st*STAGE_BYTES;
        const __half* as = Ab + (size_t)kt*64;
        #pragma unroll
        for (int it = 0; it < 4; it++) {
            const int idx = it*256 + tid;
            const int r = idx >> 3, c8 = idx & 7;
            CP_ASYNC16(a_dst + (uint32_t)(r*144 + c8*16), as + (size_t)r*K + c8*8);
        }
    };
    auto load_B = [&](int st, int kt) {
        const uint32_t b_dst = sm_b + (uint32_t)st*STAGE_BYTES + TILE_H*2;
        const __half* bs = Bb + (size_t)kt*64;
        #pragma unroll
        for (int it = 0; it < 4; it++) {
            const int idx = it*256 + tid;
            const int r = idx >> 3, c8 = idx & 7;
            CP_ASYNC16(b_dst + (uint32_t)(r*144 + c8*16), bs + (size_t)r*K + c8*8);
        }
    };

    float acc[4][4][4];
    #pragma unroll
    for (int i = 0; i < 4; i++)
        #pragma unroll
        for (int j = 0; j < 4; j++)
            #pragma unroll
            for (int k = 0; k < 4; k++) acc[i][j][k] = 0.f;

    // Weight tiles prefetch while waiting on the predecessor grid
    load_B(0, 0);
    if (nchunks > 1) load_B(1, 1);

    cudaGridDependencySynchronize();

    load_A(0, 0); CP_COMMIT();                 // group0: B0, B1, A0
    if (nchunks > 1) { load_A(1, 1); CP_COMMIT(); }   // group1: A1

    int stc = 0, pfc = GST - 1;
    for (int i = 0; i < nchunks; i++) {
        if (i + 1 < nchunks) { CP_WAIT(1); } else { CP_WAIT(0); }
        __syncthreads();

        if (i + (GST-1) < nchunks) {
            load_B(pfc, i + GST - 1);
            load_A(pfc, i + GST - 1);
            CP_COMMIT();
            if (++pfc == GST) pfc = 0;
        }

        const uint32_t aBase = sm_b + (uint32_t)stc*STAGE_BYTES;
        const uint32_t bBase = aBase + TILE_H*2;
        if (++stc == GST) stc = 0;

        #pragma unroll
        for (int kk = 0; kk < 4; kk++) {
            uint32_t a[4][4], b[2][4];
            #pragma unroll
            for (int mt = 0; mt < 4; mt++)
                LDSM_X4(a[mt][0], a[mt][1], a[mt][2], a[mt][3],
                        aBase + offA[mt] + kk*32);
            #pragma unroll
            for (int g = 0; g < 2; g++)
                LDSM_X4(b[g][0], b[g][1], b[g][2], b[g][3],
                        bBase + offB4[g] + kk*32);
            #pragma unroll
            for (int mt = 0; mt < 4; mt++) {
                #pragma unroll
                for (int g = 0; g < 2; g++) {
                    MMA_F16(acc[mt][2*g],   a[mt], b[g][0], b[g][1]);
                    MMA_F16(acc[mt][2*g+1], a[mt], b[g][2], b[g][3]);
                }
            }
        }
        // no trailing barrier: next iteration's top sync protects stage reuse
    }

    // Epilogue
    #pragma unroll
    for (int mt = 0; mt < 4; mt++) {
        #pragma unroll
        for (int nt = 0; nt < 4; nt++) {
            const int r0 = by*128 + wm*64 + mt*16 + gid;
            const int c  = bx*128 + wn*32 + nt*8 + tg*2;
            const float2 b2 = *(const float2*)(bias + c);
            #pragma unroll
            for (int half_i = 0; half_i < 2; half_i++) {
                const int r = r0 + half_i*8;
                float ox = acc[mt][nt][half_i*2+0] + b2.x;
                float oy = acc[mt][nt][half_i*2+1] + b2.y;
                if (RELU) { ox = fmaxf(ox, 0.f); oy = fmaxf(oy, 0.f); }
                if (RES) {
                    const float2 r2 = *(const float2*)(res + (size_t)r*N + c);
                    ox += r2.x; oy += r2.y;
                }
                if (HALF_OUT) {
                    *(uint32_t*)((__half*)Cv + (size_t)r*N + c) = pack_h2(ox, oy);
                } else {
                    float2 o; o.x = ox; o.y = oy;
                    *(float2*)((float*)Cv + (size_t)r*N + c) = o;
                }
            }
        }
    }
}

// ---------------------------------------------------------------------------
// fp16 tensor-core causal flash attention, d_k=64, fused QKV input.
// CTA: 256 threads (8 warps), 128 q rows (16/warp), 64-key KV tiles,
// 4-stage cp.async ring, one barrier per KV tile, K frags via ldmatrix.x4,
// warp-level skip of fully masked tiles. The softmax row-sum l is computed
// with an extra ones-column MMA per 16-key chunk (no FMA sums, no shuffles);
// exp+pack fused into the PV loop.
// ---------------------------------------------------------------------------
#define ALDH 72
#define ATILE_B (64*ALDH*2)               // 9216 B per 64x64 half tile
#define ATT_SMEM (8*ATILE_B)              // 4 stages x (K+V) = 73728 B
#define FA_C1 0.1803368801111204f          // log2(e)/8
#define ONES_H2 0x3C003C00u                // half2(1.0, 1.0)

__global__ __launch_bounds__(256, 2) void fa_kernel(
    const __half* __restrict__ QKV, __half* __restrict__ O)
{
    extern __shared__ char fsc[];
    const int tid  = threadIdx.x;
    const int lane = tid & 31, w = tid >> 5;      // 8 warps
    const int gid  = lane >> 2, tg = lane & 3;
    const int qt   = (int)gridDim.x - 1 - (int)blockIdx.x;   // big tiles first
    const int bh   = blockIdx.y;
    const int b    = bh >> 4, h = bh & 15;
    const int qbase = qt * 128;
    const int n_kt  = 2*qt + 2;                   // 64-key tiles to process

    const uint32_t fs_b = smem_u32(fsc);

    // 64-row tile loader (256 threads, 2 chunks each)
    auto load_tile = [&](uint32_t d0, const __half* src) {
        #pragma unroll
        for (int i = 0; i < 2; i++) {
            const int idx = i*256 + tid;
            const int r = idx >> 3, c8 = idx & 7;
            CP_ASYNC16(d0 + (uint32_t)(r*144 + c8*16), src + (size_t)r*QKVS + c8*8);
        }
    };

    const __half* Kg = QKV + (size_t)(b*SS)*QKVS + DM + h*DK;
    const __half* Vg = QKV + (size_t)(b*SS)*QKVS + 2*DM + h*DK;
    auto load_kv = [&](int st, int kt) {
        load_tile(fs_b + (uint32_t)st*(2*ATILE_B),           Kg + (size_t)(kt*64)*QKVS);
        load_tile(fs_b + (uint32_t)st*(2*ATILE_B) + ATILE_B, Vg + (size_t)(kt*64)*QKVS);
        CP_COMMIT();
    };

    // ldmatrix per-lane offsets
    const int la7    = lane & 7;
    const int colsel = ((lane >> 3) & 1) << 3;    // 0/8 (k half)
    const int rowsel = (lane >> 4) << 3;          // 0/8 (row pair group)
    const uint32_t offQ = (uint32_t)(((w*16 + la7 + ((lane>>3)&1)*8)*ALDH
                                     + (lane>>4)*8) * 2);
    uint32_t offK4[4];
    #pragma unroll
    for (int g = 0; g < 4; g++)
        offK4[g] = (uint32_t)(((g*16 + la7 + rowsel)*ALDH + colsel) * 2);

    cudaGridDependencySynchronize();

    // --- Stage 128-row Q tile through smem (stage 0+1 region) ---
    {
        const __half* qsrc = QKV + (size_t)(b*SS + qbase)*QKVS + h*DK;
        #pragma unroll
        for (int i = 0; i < 4; i++) {
            const int idx = i*256 + tid;
            const int r = idx >> 3, c8 = idx & 7;
            CP_ASYNC16(fs_b + (uint32_t)(r*144 + c8*16), qsrc + (size_t)r*QKVS + c8*8);
        }
        CP_COMMIT();
        CP_WAIT(0);
    }
    __syncthreads();

    uint32_t qf[4][4];
    #pragma unroll
    for (int kk = 0; kk < 4; kk++)
        LDSM_X4(qf[kk][0], qf[kk][1], qf[kk][2], qf[kk][3],
                fs_b + offQ + kk*32);
    __syncthreads();

    load_kv(0, 0);
    if (n_kt > 1) load_kv(1, 1);

    float oacc[8][4];
    #pragma unroll
    for (int d = 0; d < 8; d++) {
        oacc[d][0] = 0.f; oacc[d][1] = 0.f; oacc[d][2] = 0.f; oacc[d][3] = 0.f;
    }
    float lacc[4] = {0.f, 0.f, 0.f, 0.f};         // ones-MMA row sums
    float m0r = -INFINITY, m1r = -INFINITY;

    for (int kt = 0; kt < n_kt; kt++) {
        const int st = kt & 3;
        if (kt + 1 < n_kt) { CP_WAIT(1); } else { CP_WAIT(0); }
        __syncthreads();

        if (kt + 2 < n_kt) load_kv((kt + 2) & 3, kt + 2);

        // warps 0-3 (q rows qbase..qbase+63): last tile is fully masked
        if (kt == n_kt - 1 && w < 4) continue;

        const uint32_t ks_b = fs_b + (uint32_t)st*(2*ATILE_B);
        const uint32_t vs_b = ks_b + ATILE_B;

        // ---- S = Q K^T (unscaled), K frags via ldmatrix.x4 ----
        float sacc[8][4];
        #pragma unroll
        for (int nt = 0; nt < 8; nt++) {
            sacc[nt][0] = 0.f; sacc[nt][1] = 0.f; sacc[nt][2] = 0.f; sacc[nt][3] = 0.f;
        }
        #pragma unroll
        for (int kk = 0; kk < 4; kk++) {
            #pragma unroll
            for (int g = 0; g < 4; g++) {
                uint32_t b0, b1, b2, b3;
                LDSM_X4(b0, b1, b2, b3, ks_b + offK4[g] + kk*32);
                MMA_F16(sacc[2*g],   qf[kk], b0, b1);
                MMA_F16(sacc[2*g+1], qf[kk], b2, b3);
            }
        }

        // ---- causal mask (only where it can bite) ----
        if (kt == n_kt - 1 || (kt == n_kt - 2 && w < 4)) {
            const int koff = kt*64 - qbase;       // 0 or 64
            const int q0 = w*16 + gid;
            #pragma unroll
            for (int nt = 0; nt < 8; nt++) {
                const int s0 = koff + nt*8 + 2*tg;
                if (s0     > q0)     sacc[nt][0] = -1e30f;
                if (s0 + 1 > q0)     sacc[nt][1] = -1e30f;
                if (s0     > q0 + 8) sacc[nt][2] = -1e30f;
                if (s0 + 1 > q0 + 8) sacc[nt][3] = -1e30f;
            }
        }

        // ---- online softmax in exp2 domain ----
        float t0 = -1e30f, t1 = -1e30f;
        #pragma unroll
        for (int nt = 0; nt < 8; nt++) {
            t0 = fmaxf(t0, fmaxf(sacc[nt][0], sacc[nt][1]));
            t1 = fmaxf(t1, fmaxf(sacc[nt][2], sacc[nt][3]));
        }
        t0 = fmaxf(t0, __shfl_xor_sync(0xffffffffu, t0, 1));
        t0 = fmaxf(t0, __shfl_xor_sync(0xffffffffu, t0, 2));
        t1 = fmaxf(t1, __shfl_xor_sync(0xffffffffu, t1, 1));
        t1 = fmaxf(t1, __shfl_xor_sync(0xffffffffu, t1, 2));

        const float mn0 = fmaxf(m0r, t0), mn1 = fmaxf(m1r, t1);
        const bool chg = (mn0 > m0r) || (mn1 > m1r);
        if (__any_sync(0xffffffffu, chg)) {
            const float cr0 = ex2((m0r - mn0) * FA_C1);
            const float cr1 = ex2((m1r - mn1) * FA_C1);
            lacc[0] *= cr0; lacc[1] *= cr0; lacc[2] *= cr1; lacc[3] *= cr1;
            #pragma unroll
            for (int d = 0; d < 8; d++) {
                oacc[d][0] *= cr0; oacc[d][1] *= cr0;
                oacc[d][2] *= cr1; oacc[d][3] *= cr1;
            }
        }
        m0r = mn0; m1r = mn1;

        // ---- exp + pack + (l via ones-MMA) + O += P V, fused ----
        const float mc0 = mn0 * FA_C1, mc1 = mn1 * FA_C1;
        const int lm = lane >> 3, lr = lane & 7;
        #pragma unroll
        for (int j = 0; j < 4; j++) {
            uint32_t a[4];
            {
                const float p00 = ex2(fmaf(sacc[2*j  ][0], FA_C1, -mc0));
                const float p01 = ex2(fmaf(sacc[2*j  ][1], FA_C1, -mc0));
                const float p02 = ex2(fmaf(sacc[2*j  ][2], FA_C1, -mc1));
                const float p03 = ex2(fmaf(sacc[2*j  ][3], FA_C1, -mc1));
                const float p10 = ex2(fmaf(sacc[2*j+1][0], FA_C1, -mc0));
                const float p11 = ex2(fmaf(sacc[2*j+1][1], FA_C1, -mc0));
                const float p12 = ex2(fmaf(sacc[2*j+1][2], FA_C1, -mc1));
                const float p13 = ex2(fmaf(sacc[2*j+1][3], FA_C1, -mc1));
                a[0] = pack_h2(p00, p01);
                a[1] = pack_h2(p02, p03);
                a[2] = pack_h2(p10, p11);
                a[3] = pack_h2(p12, p13);
            }
            MMA_F16(lacc, a, ONES_H2, ONES_H2);   // row sums -> lacc
            #pragma unroll
            for (int dtp = 0; dtp < 4; dtp++) {
                const int s_a = j*16 + ((lm & 1) << 3) + lr;
                const int d_a = dtp*16 + ((lm >> 1) << 3);
                const uint32_t addr = vs_b + (uint32_t)(s_a*ALDH + d_a)*2;
                uint32_t b0, b1, b2, b3;
                LDSM_X4_TRANS(b0, b1, b2, b3, addr);
                MMA_F16(oacc[dtp*2],   a, b0, b1);
                MMA_F16(oacc[dtp*2+1], a, b2, b3);
            }
        }
        // no trailing barrier: next iteration's top sync protects stage reuse
    }

    // ---- normalize + write (fp16; feeds Wo GEMM) ----
    const float inv0 = 1.0f / lacc[0], inv1 = 1.0f / lacc[2];
    const int r0 = b*SS + qbase + w*16 + gid;
    __half* o0 = O + (size_t)r0*DM + h*DK;
    __half* o1 = o0 + (size_t)8*DM;
    #pragma unroll
    for (int dt = 0; dt < 8; dt++) {
        const int c = dt*8 + 2*tg;
        *(uint32_t*)(o0 + c) = pack_h2(oacc[dt][0]*inv0, oacc[dt][1]*inv0);
        *(uint32_t*)(o1 + c) = pack_h2(oacc[dt][2]*inv1, oacc[dt][3]*inv1);
    }
}

// ---------------------------------------------------------------------------
// PDL launch helper: ProgrammaticStreamSerialization on dependent launches
// ---------------------------------------------------------------------------
template<typename F, typename... Args>
static inline void pdl_launch(F* f, dim3 g, dim3 b, size_t smem, Args... args) {
    cudaLaunchConfig_t cfg = {};
    cfg.gridDim = g; cfg.blockDim = b; cfg.dynamicSmemBytes = smem;
    cfg.stream = 0;
    cudaLaunchAttribute at[1];
    at[0].id = cudaLaunchAttributeProgrammaticStreamSerialization;
    at[0].val.programmaticStreamSerializationAllowed = 1;
    cfg.attrs = at; cfg.numAttrs = 1;
    cudaLaunchKernelEx(&cfg, f, args...);
}

// ---------------------------------------------------------------------------
// Launch
// ---------------------------------------------------------------------------
extern "C" void kernel_launch(void* const* d_in, const int* in_sizes, int n_in,
                              void* d_out, int out_size)
{
    const float* x   = (const float*)d_in[0];
    const float* Wq  = (const float*)d_in[1];
    const float* bq  = (const float*)d_in[2];
    const float* Wk  = (const float*)d_in[3];
    const float* bk  = (const float*)d_in[4];
    const float* Wv  = (const float*)d_in[5];
    const float* bv  = (const float*)d_in[6];
    const float* Wo  = (const float*)d_in[7];
    const float* bo  = (const float*)d_in[8];
    const float* W1  = (const float*)d_in[9];
    const float* b1  = (const float*)d_in[10];
    const float* W2  = (const float*)d_in[11];
    const float* b2  = (const float*)d_in[12];
    const float* g1  = (const float*)d_in[13];
    const float* be1 = (const float*)d_in[14];
    const float* g2  = (const float*)d_in[15];
    const float* be2 = (const float*)d_in[16];
    float* out = (float*)d_out;

    __half *p_h, *p_qkv, *p_o, *p_ff;
    __half *p_wqkvt, *p_wot, *p_w1t, *p_w2t;
    float  *p_x1, *p_bqkv;
    cudaGetSymbolAddress((void**)&p_h,     g_h);
    cudaGetSymbolAddress((void**)&p_qkv,   g_qkv);
    cudaGetSymbolAddress((void**)&p_o,     g_o);
    cudaGetSymbolAddress((void**)&p_x1,    g_x1);
    cudaGetSymbolAddress((void**)&p_ff,    g_ff);
    cudaGetSymbolAddress((void**)&p_wqkvt, g_wqkvt);
    cudaGetSymbolAddress((void**)&p_wot,   g_wot);
    cudaGetSymbolAddress((void**)&p_w1t,   g_w1t);
    cudaGetSymbolAddress((void**)&p_w2t,   g_w2t);
    cudaGetSymbolAddress((void**)&p_bqkv,  g_bqkv);

    static bool attr_set = false;
    if (!attr_set) {
        cudaFuncSetAttribute(mma_gemm<false,false,true>,
                             cudaFuncAttributeMaxDynamicSharedMemorySize, GEMM_SMEM);
        cudaFuncSetAttribute(mma_gemm<false,true,false>,
                             cudaFuncAttributeMaxDynamicSharedMemorySize, GEMM_SMEM);
        cudaFuncSetAttribute(mma_gemm<true,false,true>,
                             cudaFuncAttributeMaxDynamicSharedMemorySize, GEMM_SMEM);
        cudaFuncSetAttribute(fa_kernel,
                             cudaFuncAttributeMaxDynamicSharedMemorySize, ATT_SMEM);
        attr_set = true;
    }

    // 0. single prep launch: all transposes + bias concat
    prep_kernel<<<dim3(4096, 1, 6), 256>>>(
        Wq, Wk, Wv, Wo, W1, W2,
        p_wqkvt, p_wot, p_w1t, p_w2t, bq, bk, bv, p_bqkv);

    const dim3 gQKV(QKVS/128, MROWS/128);  // (24, 64)
    const dim3 gD  (DM/128,   MROWS/128);  // (8, 64)
    const dim3 gF  (DFF/128,  MROWS/128);  // (32, 64)
    const dim3 blk(256);

    // 1. ln1(x) -> h (fp16). PLAIN launch: full serialization on prep so that
    //    downstream GEMMs may prefetch weights before their dependency sync.
    ln_kernel<<<dim3(MROWS/8), blk>>>(x, g1, be1, p_h);
    // 2. fused QKV projection (fp16 tensor pipe, N=3072)
    pdl_launch(&mma_gemm<false,false,true>, gQKV, blk, (size_t)GEMM_SMEM,
               (const __half*)p_h, (const __half*)p_wqkvt, (const float*)p_bqkv,
               (const float*)nullptr, (void*)p_qkv, MROWS, QKVS, DM);
    // 3. causal attention (fp16 flash attention, 128-row q tiles)
    pdl_launch(&fa_kernel, dim3(SS/128, BB*HH), blk, (size_t)ATT_SMEM,
               (const __half*)p_qkv, p_o);
    // 4. output projection + residual(x) -> x1 (fp32)
    pdl_launch(&mma_gemm<false,true,false>, gD, blk, (size_t)GEMM_SMEM,
               (const __half*)p_o, (const __half*)p_wot, bo,
               x, (void*)p_x1, MROWS, DM, DM);
    // 5. ln2(x1) -> h (fp16)
    pdl_launch(&ln_kernel, dim3(MROWS/8), blk, 0,
               (const float*)p_x1, g2, be2, p_h);
    // 6. FFN up + ReLU (fp16 out)
    pdl_launch(&mma_gemm<true,false,true>, gF, blk, (size_t)GEMM_SMEM,
               (const __half*)p_h, (const __half*)p_w1t, b1,
               (const float*)nullptr, (void*)p_ff, MROWS, DFF, DM);
    // 7. FFN down + residual(x1) -> out (fp32)
    pdl_launch(&mma_gemm<false,true,false>, gD, blk, (size_t)GEMM_SMEM,
               (const __half*)p_ff, (const __half*)p_w2t, b2,
               (const float*)p_x1, (void*)out, MROWS, DM, DFF);
}

// round 15
// speedup vs baseline: 1.0126x; 1.0126x over previous
#include <cuda_runtime.h>
#include <cuda_fp16.h>
#include <math.h>
#include <stdint.h>

// Problem dimensions (fixed by the reference)
#define BB    4
#define SS    2048
#define DM    1024
#define HH    16
#define DK    64
#define DFF   4096
#define MROWS (BB*SS)          // 8192
#define QKVS  3072             // fused QKV row stride
#define LN_EPS 1e-5f

// ---------------------------------------------------------------------------
// Scratch (device globals; no allocations allowed)
// ---------------------------------------------------------------------------
__device__ __half g_h   [MROWS*DM];     // ln1 / ln2 output (fp16)
__device__ __half g_qkv [MROWS*QKVS];   // fused Q|K|V (fp16)
__device__ __half g_o   [MROWS*DM];     // attention output (fp16)
__device__ float  g_x1  [MROWS*DM];     // residual after attention (fp32)
__device__ __half g_ff  [MROWS*DFF];    // FFN hidden (fp16)
__device__ __half g_wqkvt[QKVS*DM];     // fused transposed weights [3072,1024]
__device__ __half g_wot [DM*DM];
__device__ __half g_w1t [DFF*DM];       // [4096,1024]
__device__ __half g_w2t [DM*DFF];       // [1024,4096]
__device__ float  g_bqkv[QKVS];         // fused bias

// ---------------------------------------------------------------------------
// Helpers
// ---------------------------------------------------------------------------
__device__ __forceinline__ uint32_t smem_u32(const void* p) {
    uint32_t a;
    asm("{ .reg .u64 t; cvta.to.shared.u64 t, %1; cvt.u32.u64 %0, t; }"
        : "=r"(a) : "l"(p));
    return a;
}

__device__ __forceinline__ uint32_t pack_h2(float lo, float hi) {
    __half2 h = __floats2half2_rn(lo, hi);
    return *reinterpret_cast<uint32_t*>(&h);
}

__device__ __forceinline__ float ex2(float x) {        // 2^x, MUFU.EX2
    float y;
    asm("ex2.approx.f32 %0, %1;" : "=f"(y) : "f"(x));
    return y;
}

#define CP_ASYNC16(dst, src) \
    asm volatile("cp.async.cg.shared.global [%0], [%1], 16;" :: "r"(dst), "l"(src))
#define CP_COMMIT()  asm volatile("cp.async.commit_group;" ::: "memory")
#define CP_WAIT(n)   asm volatile("cp.async.wait_group %0;" :: "n"(n) : "memory")

// m16n8k16 fp16 mma, fp32 accumulate
#define MMA_F16(d, a, b0, b1) \
    asm volatile("mma.sync.aligned.m16n8k16.row.col.f32.f16.f16.f32 " \
        "{%0,%1,%2,%3}, {%4,%5,%6,%7}, {%8,%9}, {%0,%1,%2,%3};" \
        : "+f"(d[0]), "+f"(d[1]), "+f"(d[2]), "+f"(d[3]) \
        : "r"(a[0]), "r"(a[1]), "r"(a[2]), "r"(a[3]), "r"(b0), "r"(b1))

#define LDSM_X4(r0, r1, r2, r3, addr) \
    asm volatile("ldmatrix.sync.aligned.m8n8.x4.shared.b16 {%0,%1,%2,%3}, [%4];" \
        : "=r"(r0), "=r"(r1), "=r"(r2), "=r"(r3) : "r"(addr))

#define LDSM_X4_TRANS(r0, r1, r2, r3, addr) \
    asm volatile("ldmatrix.sync.aligned.m8n8.x4.trans.shared.b16 {%0,%1,%2,%3}, [%4];" \
        : "=r"(r0), "=r"(r1), "=r"(r2), "=r"(r3) : "r"(addr))

// ---------------------------------------------------------------------------
// LayerNorm -> fp16, warp-per-row (8 rows per 256-thread block, no barriers)
// ---------------------------------------------------------------------------
__global__ __launch_bounds__(256) void ln_kernel(
    const float* __restrict__ X, const float* __restrict__ gamma,
    const float* __restrict__ beta, __half* __restrict__ out)
{
    const int t = threadIdx.x, lane = t & 31, w = t >> 5;
    const int row = blockIdx.x*8 + w;

    cudaGridDependencySynchronize();

    const float4* Xr = (const float4*)(X + (size_t)row*DM);
    float4 v[8];
    float s = 0.f, ss = 0.f;
    #pragma unroll
    for (int i = 0; i < 8; i++) {
        v[i] = Xr[lane + i*32];
        s  += v[i].x + v[i].y + v[i].z + v[i].w;
        ss += v[i].x*v[i].x + v[i].y*v[i].y + v[i].z*v[i].z + v[i].w*v[i].w;
    }
    #pragma unroll
    for (int o = 16; o > 0; o >>= 1) {
        s  += __shfl_xor_sync(0xffffffffu, s,  o);
        ss += __shfl_xor_sync(0xffffffffu, ss, o);
    }
    const float mu   = s * (1.0f / DM);
    const float var  = ss * (1.0f / DM) - mu*mu;
    const float rstd = rsqrtf(var + LN_EPS);

    const float4* G  = (const float4*)gamma;
    const float4* Bt = (const float4*)beta;
    uint2* Or = (uint2*)(out + (size_t)row*DM);
    #pragma unroll
    for (int i = 0; i < 8; i++) {
        const float4 g4 = G[lane + i*32];
        const float4 b4 = Bt[lane + i*32];
        uint2 st;
        st.x = pack_h2((v[i].x - mu)*rstd*g4.x + b4.x,
                       (v[i].y - mu)*rstd*g4.y + b4.y);
        st.y = pack_h2((v[i].z - mu)*rstd*g4.z + b4.z,
                       (v[i].w - mu)*rstd*g4.w + b4.w);
        Or[lane + i*32] = st;
    }
}

// ---------------------------------------------------------------------------
// Single prep kernel: z=0..5 -> transpose+round of Wq/Wk/Wv/Wo/W1/W2,
// bias concat folded into z=0 blocks 1024..1035. Grid (4096,1,6), block 256.
// ---------------------------------------------------------------------------
__global__ __launch_bounds__(256) void prep_kernel(
    const float* __restrict__ Wq, const float* __restrict__ Wk,
    const float* __restrict__ Wv, const float* __restrict__ Wo,
    const float* __restrict__ W1, const float* __restrict__ W2,
    __half* __restrict__ Tqkv, __half* __restrict__ To,
    __half* __restrict__ T1, __half* __restrict__ T2,
    const float* __restrict__ bq, const float* __restrict__ bk,
    const float* __restrict__ bv, float* __restrict__ bqkv)
{
    const int z = blockIdx.z;
    const float* W; __half* T; int K, N;
    switch (z) {
        case 0:  W = Wq; T = Tqkv;           K = DM;  N = DM;  break;
        case 1:  W = Wk; T = Tqkv + DM*DM;   K = DM;  N = DM;  break;
        case 2:  W = Wv; T = Tqkv + 2*DM*DM; K = DM;  N = DM;  break;
        case 3:  W = Wo; T = To;             K = DM;  N = DM;  break;
        case 4:  W = W1; T = T1;             K = DM;  N = DFF; break;
        default: W = W2; T = T2;             K = DFF; N = DM;  break;
    }
    // bias concat on z=0 blocks 1024..1035
    if (z == 0 && blockIdx.x >= 1024) {
        if (blockIdx.x < 1036) {
            const int i = (blockIdx.x - 1024)*256 + threadIdx.x;
            if (i < DM)        bqkv[i] = bq[i];
            else if (i < 2*DM) bqkv[i] = bk[i - DM];
            else               bqkv[i] = bv[i - 2*DM];
        }
        return;
    }
    const int nblk = N >> 5;
    const int bx = blockIdx.x % nblk, byk = blockIdx.x / nblk;
    if (byk >= (K >> 5)) return;

    __shared__ float tile[32][33];
    const int tx = threadIdx.x & 31, ty = threadIdx.x >> 5;
    const int n0 = bx*32, k0 = byk*32;
    #pragma unroll
    for (int i = ty; i < 32; i += 8)
        tile[i][tx] = W[(size_t)(k0 + i)*N + n0 + tx];
    __syncthreads();
    #pragma unroll
    for (int i = ty; i < 32; i += 8)
        T[(size_t)(n0 + i)*K + k0 + tx] = __float2half_rn(tile[tx][i]);
}

// ---------------------------------------------------------------------------
// fp16 mma.sync GEMM (R13 form): C[M,N] = A[M,K] @ Bt[N,K]^T + bias
// 128x128 CTA tile, BK=64, 3-stage cp.async, 256 threads (8 warps, 2x4),
// warp tile 64x32, ldmatrix x4 fragments (A and B), 2 CTAs/SM.
// ---------------------------------------------------------------------------
#define GST    3
#define LDH    72
#define TILE_H (128*LDH)                 // halves per tile (9216)
#define STAGE_BYTES (2*TILE_H*2)         // A + B = 36864 B
#define GEMM_SMEM (GST*STAGE_BYTES)      // 110592 B

template<bool RELU, bool RES, bool HALF_OUT>
__global__ __launch_bounds__(256, 2) void mma_gemm(
    const __half* __restrict__ A, const __half* __restrict__ Bt,
    const float* __restrict__ bias, const float* __restrict__ res,
    void* __restrict__ Cv, int M, int N, int K)
{
    extern __shared__ char smc[];
    const uint32_t sm_b = smem_u32(smc);

    const int tid  = threadIdx.x;
    const int lane = tid & 31, wid = tid >> 5;
    const int wm = wid >> 2, wn = wid & 3;        // 2 x 4 warp grid
    const int gid = lane >> 2, tg = lane & 3;
    const int bx = blockIdx.x, by = blockIdx.y;

    const __half* Ab = A  + (size_t)by * 128 * K;
    const __half* Bb = Bt + (size_t)bx * 128 * K;
    const int nchunks = K >> 6;                   // K/64

    // ldmatrix per-lane offsets (bytes) within a stage's A / B tile
    const int la7    = lane & 7;
    const int colsel = ((lane >> 3) & 1) << 3;    // 0/8 (k half)
    const int rowsel = (lane >> 4) << 3;          // 0/8 (row group)
    uint32_t offA[4], offB4[2];
    {
        const int arow = la7 + ((lane >> 3) & 1) * 8;
        const int acol = (lane >> 4) * 8;
        #pragma unroll
        for (int mt = 0; mt < 4; mt++)
            offA[mt] = (uint32_t)(((wm*64 + mt*16 + arow)*LDH + acol) * 2);
        #pragma unroll
        for (int g = 0; g < 2; g++)
            offB4[g] = (uint32_t)(((wn*32 + g*16 + la7 + rowsel)*LDH + colsel) * 2);
    }

    // Stage loader: 2 tiles x 128 rows x 64 halves (8x16B per row)
    auto load_stage = [&](int st, int kt) {
        const uint32_t a_dst = sm_b + (uint32_t)st*STAGE_BYTES;
        const uint32_t b_dst = a_dst + TILE_H*2;
        const __half* as = Ab + (size_t)kt*64;
        const __half* bs = Bb + (size_t)kt*64;
        #pragma unroll
        for (int it = 0; it < 4; it++) {
            const int idx = it*256 + tid;
            const int r = idx >> 3, c8 = idx & 7;
            const uint32_t off = (uint32_t)(r*144 + c8*16);
            CP_ASYNC16(a_dst + off, as + (size_t)r*K + c8*8);
            CP_ASYNC16(b_dst + off, bs + (size_t)r*K + c8*8);
        }
        CP_COMMIT();
    };

    float acc[4][4][4];
    #pragma unroll
    for (int i = 0; i < 4; i++)
        #pragma unroll
        for (int j = 0; j < 4; j++)
            #pragma unroll
            for (int k = 0; k < 4; k++) acc[i][j][k] = 0.f;

    cudaGridDependencySynchronize();

    load_stage(0, 0);
    if (nchunks > 1) load_stage(1, 1);

    for (int i = 0; i < nchunks; i++) {
        const int st = i % GST;
        if (i + 1 < nchunks) { CP_WAIT(1); } else { CP_WAIT(0); }
        __syncthreads();

        if (i + (GST-1) < nchunks)
            load_stage((i + GST - 1) % GST, i + GST - 1);

        const uint32_t aBase = sm_b + (uint32_t)st*STAGE_BYTES;
        const uint32_t bBase = aBase + TILE_H*2;

        #pragma unroll
        for (int kk = 0; kk < 4; kk++) {
            uint32_t a[4][4], b[2][4];
            #pragma unroll
            for (int mt = 0; mt < 4; mt++)
                LDSM_X4(a[mt][0], a[mt][1], a[mt][2], a[mt][3],
                        aBase + offA[mt] + kk*32);
            #pragma unroll
            for (int g = 0; g < 2; g++)
                LDSM_X4(b[g][0], b[g][1], b[g][2], b[g][3],
                        bBase + offB4[g] + kk*32);
            #pragma unroll
            for (int mt = 0; mt < 4; mt++) {
                #pragma unroll
                for (int g = 0; g < 2; g++) {
                    MMA_F16(acc[mt][2*g],   a[mt], b[g][0], b[g][1]);
                    MMA_F16(acc[mt][2*g+1], a[mt], b[g][2], b[g][3]);
                }
            }
        }
        // no trailing barrier: next iteration's top sync protects stage reuse
    }

    // Epilogue
    #pragma unroll
    for (int mt = 0; mt < 4; mt++) {
        #pragma unroll
        for (int nt = 0; nt < 4; nt++) {
            const int r0 = by*128 + wm*64 + mt*16 + gid;
            const int c  = bx*128 + wn*32 + nt*8 + tg*2;
            const float2 b2 = *(const float2*)(bias + c);
            #pragma unroll
            for (int half_i = 0; half_i < 2; half_i++) {
                const int r = r0 + half_i*8;
                float ox = acc[mt][nt][half_i*2+0] + b2.x;
                float oy = acc[mt][nt][half_i*2+1] + b2.y;
                if (RELU) { ox = fmaxf(ox, 0.f); oy = fmaxf(oy, 0.f); }
                if (RES) {
                    const float2 r2 = *(const float2*)(res + (size_t)r*N + c);
                    ox += r2.x; oy += r2.y;
                }
                if (HALF_OUT) {
                    *(uint32_t*)((__half*)Cv + (size_t)r*N + c) = pack_h2(ox, oy);
                } else {
                    float2 o; o.x = ox; o.y = oy;
                    *(float2*)((float*)Cv + (size_t)r*N + c) = o;
                }
            }
        }
    }
}

// ---------------------------------------------------------------------------
// fp16 tensor-core causal flash attention, d_k=64, fused QKV input.
// CTA: 256 threads (8 warps), 128 q rows (16/warp), 64-key KV tiles,
// 4-stage cp.async ring, one barrier per KV tile, K frags via ldmatrix.x4,
// warp-level skip of fully masked tiles. Softmax row-sum l via ones-column
// MMA per 16-key chunk (no FMA sums, no shuffles); exp+pack fused into PV.
// ---------------------------------------------------------------------------
#define ALDH 72
#define ATILE_B (64*ALDH*2)               // 9216 B per 64x64 half tile
#define ATT_SMEM (8*ATILE_B)              // 4 stages x (K+V) = 73728 B
#define FA_C1 0.1803368801111204f          // log2(e)/8
#define ONES_H2 0x3C003C00u                // half2(1.0, 1.0)

__global__ __launch_bounds__(256, 2) void fa_kernel(
    const __half* __restrict__ QKV, __half* __restrict__ O)
{
    extern __shared__ char fsc[];
    const int tid  = threadIdx.x;
    const int lane = tid & 31, w = tid >> 5;      // 8 warps
    const int gid  = lane >> 2, tg = lane & 3;
    const int qt   = (int)gridDim.x - 1 - (int)blockIdx.x;   // big tiles first
    const int bh   = blockIdx.y;
    const int b    = bh >> 4, h = bh & 15;
    const int qbase = qt * 128;
    const int n_kt  = 2*qt + 2;                   // 64-key tiles to process

    const uint32_t fs_b = smem_u32(fsc);

    // 64-row tile loader (256 threads, 2 chunks each)
    auto load_tile = [&](uint32_t d0, const __half* src) {
        #pragma unroll
        for (int i = 0; i < 2; i++) {
            const int idx = i*256 + tid;
            const int r = idx >> 3, c8 = idx & 7;
            CP_ASYNC16(d0 + (uint32_t)(r*144 + c8*16), src + (size_t)r*QKVS + c8*8);
        }
    };

    const __half* Kg = QKV + (size_t)(b*SS)*QKVS + DM + h*DK;
    const __half* Vg = QKV + (size_t)(b*SS)*QKVS + 2*DM + h*DK;
    auto load_kv = [&](int st, int kt) {
        load_tile(fs_b + (uint32_t)st*(2*ATILE_B),           Kg + (size_t)(kt*64)*QKVS);
        load_tile(fs_b + (uint32_t)st*(2*ATILE_B) + ATILE_B, Vg + (size_t)(kt*64)*QKVS);
        CP_COMMIT();
    };

    // ldmatrix per-lane offsets
    const int la7    = lane & 7;
    const int colsel = ((lane >> 3) & 1) << 3;    // 0/8 (k half)
    const int rowsel = (lane >> 4) << 3;          // 0/8 (row pair group)
    const uint32_t offQ = (uint32_t)(((w*16 + la7 + ((lane>>3)&1)*8)*ALDH
                                     + (lane>>4)*8) * 2);
    uint32_t offK4[4];
    #pragma unroll
    for (int g = 0; g < 4; g++)
        offK4[g] = (uint32_t)(((g*16 + la7 + rowsel)*ALDH + colsel) * 2);

    cudaGridDependencySynchronize();

    // --- Stage 128-row Q tile through smem (stage 0+1 region) ---
    {
        const __half* qsrc = QKV + (size_t)(b*SS + qbase)*QKVS + h*DK;
        #pragma unroll
        for (int i = 0; i < 4; i++) {
            const int idx = i*256 + tid;
            const int r = idx >> 3, c8 = idx & 7;
            CP_ASYNC16(fs_b + (uint32_t)(r*144 + c8*16), qsrc + (size_t)r*QKVS + c8*8);
        }
        CP_COMMIT();
        CP_WAIT(0);
    }
    __syncthreads();

    uint32_t qf[4][4];
    #pragma unroll
    for (int kk = 0; kk < 4; kk++)
        LDSM_X4(qf[kk][0], qf[kk][1], qf[kk][2], qf[kk][3],
                fs_b + offQ + kk*32);
    __syncthreads();

    load_kv(0, 0);
    if (n_kt > 1) load_kv(1, 1);

    float oacc[8][4];
    #pragma unroll
    for (int d = 0; d < 8; d++) {
        oacc[d][0] = 0.f; oacc[d][1] = 0.f; oacc[d][2] = 0.f; oacc[d][3] = 0.f;
    }
    float lacc[4] = {0.f, 0.f, 0.f, 0.f};         // ones-MMA row sums
    float m0r = -INFINITY, m1r = -INFINITY;

    for (int kt = 0; kt < n_kt; kt++) {
        const int st = kt & 3;
        if (kt + 1 < n_kt) { CP_WAIT(1); } else { CP_WAIT(0); }
        __syncthreads();

        if (kt + 2 < n_kt) load_kv((kt + 2) & 3, kt + 2);

        // warps 0-3 (q rows qbase..qbase+63): last tile is fully masked
        if (kt == n_kt - 1 && w < 4) continue;

        const uint32_t ks_b = fs_b + (uint32_t)st*(2*ATILE_B);
        const uint32_t vs_b = ks_b + ATILE_B;

        // ---- S = Q K^T (unscaled), K frags via ldmatrix.x4 ----
        float sacc[8][4];
        #pragma unroll
        for (int nt = 0; nt < 8; nt++) {
            sacc[nt][0] = 0.f; sacc[nt][1] = 0.f; sacc[nt][2] = 0.f; sacc[nt][3] = 0.f;
        }
        #pragma unroll
        for (int kk = 0; kk < 4; kk++) {
            #pragma unroll
            for (int g = 0; g < 4; g++) {
                uint32_t b0, b1, b2, b3;
                LDSM_X4(b0, b1, b2, b3, ks_b + offK4[g] + kk*32);
                MMA_F16(sacc[2*g],   qf[kk], b0, b1);
                MMA_F16(sacc[2*g+1], qf[kk], b2, b3);
            }
        }

        // ---- causal mask (only where it can bite) ----
        if (kt == n_kt - 1 || (kt == n_kt - 2 && w < 4)) {
            const int koff = kt*64 - qbase;       // 0 or 64
            const int q0 = w*16 + gid;
            #pragma unroll
            for (int nt = 0; nt < 8; nt++) {
                const int s0 = koff + nt*8 + 2*tg;
                if (s0     > q0)     sacc[nt][0] = -1e30f;
                if (s0 + 1 > q0)     sacc[nt][1] = -1e30f;
                if (s0     > q0 + 8) sacc[nt][2] = -1e30f;
                if (s0 + 1 > q0 + 8) sacc[nt][3] = -1e30f;
            }
        }

        // ---- online softmax in exp2 domain ----
        float t0 = -1e30f, t1 = -1e30f;
        #pragma unroll
        for (int nt = 0; nt < 8; nt++) {
            t0 = fmaxf(t0, fmaxf(sacc[nt][0], sacc[nt][1]));
            t1 = fmaxf(t1, fmaxf(sacc[nt][2], sacc[nt][3]));
        }
        t0 = fmaxf(t0, __shfl_xor_sync(0xffffffffu, t0, 1));
        t0 = fmaxf(t0, __shfl_xor_sync(0xffffffffu, t0, 2));
        t1 = fmaxf(t1, __shfl_xor_sync(0xffffffffu, t1, 1));
        t1 = fmaxf(t1, __shfl_xor_sync(0xffffffffu, t1, 2));

        const float mn0 = fmaxf(m0r, t0), mn1 = fmaxf(m1r, t1);
        const bool chg = (mn0 > m0r) || (mn1 > m1r);
        if (__any_sync(0xffffffffu, chg)) {
            const float cr0 = ex2((m0r - mn0) * FA_C1);
            const float cr1 = ex2((m1r - mn1) * FA_C1);
            lacc[0] *= cr0; lacc[1] *= cr0; lacc[2] *= cr1; lacc[3] *= cr1;
            #pragma unroll
            for (int d = 0; d < 8; d++) {
                oacc[d][0] *= cr0; oacc[d][1] *= cr0;
                oacc[d][2] *= cr1; oacc[d][3] *= cr1;
            }
        }
        m0r = mn0; m1r = mn1;

        // ---- exp + pack + (l via ones-MMA) + O += P V, fused ----
        const float mc0 = mn0 * FA_C1, mc1 = mn1 * FA_C1;
        const int lm = lane >> 3, lr = lane & 7;
        #pragma unroll
        for (int j = 0; j < 4; j++) {
            uint32_t a[4];
            {
                const float p00 = ex2(fmaf(sacc[2*j  ][0], FA_C1, -mc0));
                const float p01 = ex2(fmaf(sacc[2*j  ][1], FA_C1, -mc0));
                const float p02 = ex2(fmaf(sacc[2*j  ][2], FA_C1, -mc1));
                const float p03 = ex2(fmaf(sacc[2*j  ][3], FA_C1, -mc1));
                const float p10 = ex2(fmaf(sacc[2*j+1][0], FA_C1, -mc0));
                const float p11 = ex2(fmaf(sacc[2*j+1][1], FA_C1, -mc0));
                const float p12 = ex2(fmaf(sacc[2*j+1][2], FA_C1, -mc1));
                const float p13 = ex2(fmaf(sacc[2*j+1][3], FA_C1, -mc1));
                a[0] = pack_h2(p00, p01);
                a[1] = pack_h2(p02, p03);
                a[2] = pack_h2(p10, p11);
                a[3] = pack_h2(p12, p13);
            }
            MMA_F16(lacc, a, ONES_H2, ONES_H2);   // row sums -> lacc
            #pragma unroll
            for (int dtp = 0; dtp < 4; dtp++) {
                const int s_a = j*16 + ((lm & 1) << 3) + lr;
                const int d_a = dtp*16 + ((lm >> 1) << 3);
                const uint32_t addr = vs_b + (uint32_t)(s_a*ALDH + d_a)*2;
                uint32_t b0, b1, b2, b3;
                LDSM_X4_TRANS(b0, b1, b2, b3, addr);
                MMA_F16(oacc[dtp*2],   a, b0, b1);
                MMA_F16(oacc[dtp*2+1], a, b2, b3);
            }
        }
        // no trailing barrier: next iteration's top sync protects stage reuse
    }

    // ---- normalize + write (fp16; feeds Wo GEMM) ----
    const float inv0 = 1.0f / lacc[0], inv1 = 1.0f / lacc[2];
    const int r0 = b*SS + qbase + w*16 + gid;
    __half* o0 = O + (size_t)r0*DM + h*DK;
    __half* o1 = o0 + (size_t)8*DM;
    #pragma unroll
    for (int dt = 0; dt < 8; dt++) {
        const int c = dt*8 + 2*tg;
        *(uint32_t*)(o0 + c) = pack_h2(oacc[dt][0]*inv0, oacc[dt][1]*inv0);
        *(uint32_t*)(o1 + c) = pack_h2(oacc[dt][2]*inv1, oacc[dt][3]*inv1);
    }
}

// ---------------------------------------------------------------------------
// PDL launch helper: ProgrammaticStreamSerialization on dependent launches
// ---------------------------------------------------------------------------
template<typename F, typename... Args>
static inline void pdl_launch(F* f, dim3 g, dim3 b, size_t smem, Args... args) {
    cudaLaunchConfig_t cfg = {};
    cfg.gridDim = g; cfg.blockDim = b; cfg.dynamicSmemBytes = smem;
    cfg.stream = 0;
    cudaLaunchAttribute at[1];
    at[0].id = cudaLaunchAttributeProgrammaticStreamSerialization;
    at[0].val.programmaticStreamSerializationAllowed = 1;
    cfg.attrs = at; cfg.numAttrs = 1;
    cudaLaunchKernelEx(&cfg, f, args...);
}

// ---------------------------------------------------------------------------
// Launch
// ---------------------------------------------------------------------------
extern "C" void kernel_launch(void* const* d_in, const int* in_sizes, int n_in,
                              void* d_out, int out_size)
{
    const float* x   = (const float*)d_in[0];
    const float* Wq  = (const float*)d_in[1];
    const float* bq  = (const float*)d_in[2];
    const float* Wk  = (const float*)d_in[3];
    const float* bk  = (const float*)d_in[4];
    const float* Wv  = (const float*)d_in[5];
    const float* bv  = (const float*)d_in[6];
    const float* Wo  = (const float*)d_in[7];
    const float* bo  = (const float*)d_in[8];
    const float* W1  = (const float*)d_in[9];
    const float* b1  = (const float*)d_in[10];
    const float* W2  = (const float*)d_in[11];
    const float* b2  = (const float*)d_in[12];
    const float* g1  = (const float*)d_in[13];
    const float* be1 = (const float*)d_in[14];
    const float* g2  = (const float*)d_in[15];
    const float* be2 = (const float*)d_in[16];
    float* out = (float*)d_out;

    __half *p_h, *p_qkv, *p_o, *p_ff;
    __half *p_wqkvt, *p_wot, *p_w1t, *p_w2t;
    float  *p_x1, *p_bqkv;
    cudaGetSymbolAddress((void**)&p_h,     g_h);
    cudaGetSymbolAddress((void**)&p_qkv,   g_qkv);
    cudaGetSymbolAddress((void**)&p_o,     g_o);
    cudaGetSymbolAddress((void**)&p_x1,    g_x1);
    cudaGetSymbolAddress((void**)&p_ff,    g_ff);
    cudaGetSymbolAddress((void**)&p_wqkvt, g_wqkvt);
    cudaGetSymbolAddress((void**)&p_wot,   g_wot);
    cudaGetSymbolAddress((void**)&p_w1t,   g_w1t);
    cudaGetSymbolAddress((void**)&p_w2t,   g_w2t);
    cudaGetSymbolAddress((void**)&p_bqkv,  g_bqkv);

    static bool attr_set = false;
    if (!attr_set) {
        cudaFuncSetAttribute(mma_gemm<false,false,true>,
                             cudaFuncAttributeMaxDynamicSharedMemorySize, GEMM_SMEM);
        cudaFuncSetAttribute(mma_gemm<false,true,false>,
                             cudaFuncAttributeMaxDynamicSharedMemorySize, GEMM_SMEM);
        cudaFuncSetAttribute(mma_gemm<true,false,true>,
                             cudaFuncAttributeMaxDynamicSharedMemorySize, GEMM_SMEM);
        cudaFuncSetAttribute(fa_kernel,
                             cudaFuncAttributeMaxDynamicSharedMemorySize, ATT_SMEM);
        attr_set = true;
    }

    // 0. single prep launch: all transposes + bias concat
    prep_kernel<<<dim3(4096, 1, 6), 256>>>(
        Wq, Wk, Wv, Wo, W1, W2,
        p_wqkvt, p_wot, p_w1t, p_w2t, bq, bk, bv, p_bqkv);

    const dim3 gQKV(QKVS/128, MROWS/128);  // (24, 64)
    const dim3 gD  (DM/128,   MROWS/128);  // (8, 64)
    const dim3 gF  (DFF/128,  MROWS/128);  // (32, 64)
    const dim3 blk(256);

    // 1. ln1(x) -> h (fp16)
    pdl_launch(&ln_kernel, dim3(MROWS/8), blk, 0, x, g1, be1, p_h);
    // 2. fused QKV projection (fp16 tensor pipe, N=3072)
    pdl_launch(&mma_gemm<false,false,true>, gQKV, blk, (size_t)GEMM_SMEM,
               (const __half*)p_h, (const __half*)p_wqkvt, (const float*)p_bqkv,
               (const float*)nullptr, (void*)p_qkv, MROWS, QKVS, DM);
    // 3. causal attention (fp16 flash attention, 128-row q tiles)
    pdl_launch(&fa_kernel, dim3(SS/128, BB*HH), blk, (size_t)ATT_SMEM,
               (const __half*)p_qkv, p_o);
    // 4. output projection + residual(x) -> x1 (fp32)
    pdl_launch(&mma_gemm<false,true,false>, gD, blk, (size_t)GEMM_SMEM,
               (const __half*)p_o, (const __half*)p_wot, bo,
               x, (void*)p_x1, MROWS, DM, DM);
    // 5. ln2(x1) -> h (fp16)
    pdl_launch(&ln_kernel, dim3(MROWS/8), blk, 0,
               (const float*)p_x1, g2, be2, p_h);
    // 6. FFN up + ReLU (fp16 out)
    pdl_launch(&mma_gemm<true,false,true>, gF, blk, (size_t)GEMM_SMEM,
               (const __half*)p_h, (const __half*)p_w1t, b1,
               (const float*)nullptr, (void*)p_ff, MROWS, DFF, DM);
    // 7. FFN down + residual(x1) -> out (fp32)
    pdl_launch(&mma_gemm<false,true,false>, gD, blk, (size_t)GEMM_SMEM,
               (const __half*)p_ff, (const __half*)p_w2t, b2,
               (const float*)p_x1, (void*)out, MROWS, DM, DFF);
}

// round 16
// speedup vs baseline: 1.0152x; 1.0026x over previous
#include <cuda_runtime.h>
#include <cuda_fp16.h>
#include <math.h>
#include <stdint.h>

// Problem dimensions (fixed by the reference)
#define BB    4
#define SS    2048
#define DM    1024
#define HH    16
#define DK    64
#define DFF   4096
#define MROWS (BB*SS)          // 8192
#define QKVS  3072             // fused QKV row stride
#define LN_EPS 1e-5f

// ---------------------------------------------------------------------------
// Scratch (device globals; no allocations allowed)
// ---------------------------------------------------------------------------
__device__ __half g_h   [MROWS*DM];     // ln1 / ln2 output (fp16)
__device__ __half g_qkv [MROWS*QKVS];   // fused Q|K|V (fp16)
__device__ __half g_o   [MROWS*DM];     // attention output (fp16)
__device__ float  g_x1  [MROWS*DM];     // residual after attention (fp32)
__device__ __half g_ff  [MROWS*DFF];    // FFN hidden (fp16)
__device__ __half g_wqkvt[QKVS*DM];     // fused transposed weights [3072,1024]
__device__ __half g_wot [DM*DM];
__device__ __half g_w1t [DFF*DM];       // [4096,1024]
__device__ __half g_w2t [DM*DFF];       // [1024,4096]
__device__ float  g_bqkv[QKVS];         // fused bias

// ---------------------------------------------------------------------------
// Helpers
// ---------------------------------------------------------------------------
__device__ __forceinline__ uint32_t smem_u32(const void* p) {
    uint32_t a;
    asm("{ .reg .u64 t; cvta.to.shared.u64 t, %1; cvt.u32.u64 %0, t; }"
        : "=r"(a) : "l"(p));
    return a;
}

__device__ __forceinline__ uint32_t pack_h2(float lo, float hi) {
    __half2 h = __floats2half2_rn(lo, hi);
    return *reinterpret_cast<uint32_t*>(&h);
}

__device__ __forceinline__ float ex2(float x) {        // 2^x, MUFU.EX2
    float y;
    asm("ex2.approx.f32 %0, %1;" : "=f"(y) : "f"(x));
    return y;
}

#define CP_ASYNC16(dst, src) \
    asm volatile("cp.async.cg.shared.global [%0], [%1], 16;" :: "r"(dst), "l"(src))
#define CP_COMMIT()  asm volatile("cp.async.commit_group;" ::: "memory")
#define CP_WAIT(n)   asm volatile("cp.async.wait_group %0;" :: "n"(n) : "memory")

// m16n8k16 fp16 mma, fp32 accumulate
#define MMA_F16(d, a, b0, b1) \
    asm volatile("mma.sync.aligned.m16n8k16.row.col.f32.f16.f16.f32 " \
        "{%0,%1,%2,%3}, {%4,%5,%6,%7}, {%8,%9}, {%0,%1,%2,%3};" \
        : "+f"(d[0]), "+f"(d[1]), "+f"(d[2]), "+f"(d[3]) \
        : "r"(a[0]), "r"(a[1]), "r"(a[2]), "r"(a[3]), "r"(b0), "r"(b1))

// zero-C variant: d = a*b (no accumulator read; C operands are zeros)
#define MMA_F16_Z(d, a, b0, b1, z) \
    asm volatile("mma.sync.aligned.m16n8k16.row.col.f32.f16.f16.f32 " \
        "{%0,%1,%2,%3}, {%4,%5,%6,%7}, {%8,%9}, {%10,%10,%10,%10};" \
        : "=f"(d[0]), "=f"(d[1]), "=f"(d[2]), "=f"(d[3]) \
        : "r"(a[0]), "r"(a[1]), "r"(a[2]), "r"(a[3]), "r"(b0), "r"(b1), "f"(z))

#define LDSM_X4(r0, r1, r2, r3, addr) \
    asm volatile("ldmatrix.sync.aligned.m8n8.x4.shared.b16 {%0,%1,%2,%3}, [%4];" \
        : "=r"(r0), "=r"(r1), "=r"(r2), "=r"(r3) : "r"(addr))

#define LDSM_X4_TRANS(r0, r1, r2, r3, addr) \
    asm volatile("ldmatrix.sync.aligned.m8n8.x4.trans.shared.b16 {%0,%1,%2,%3}, [%4];" \
        : "=r"(r0), "=r"(r1), "=r"(r2), "=r"(r3) : "r"(addr))

// ---------------------------------------------------------------------------
// LayerNorm -> fp16, warp-per-row (8 rows per 256-thread block, no barriers)
// ---------------------------------------------------------------------------
__global__ __launch_bounds__(256) void ln_kernel(
    const float* __restrict__ X, const float* __restrict__ gamma,
    const float* __restrict__ beta, __half* __restrict__ out)
{
    const int t = threadIdx.x, lane = t & 31, w = t >> 5;
    const int row = blockIdx.x*8 + w;

    cudaGridDependencySynchronize();

    const float4* Xr = (const float4*)(X + (size_t)row*DM);
    float4 v[8];
    float s = 0.f, ss = 0.f;
    #pragma unroll
    for (int i = 0; i < 8; i++) {
        v[i] = Xr[lane + i*32];
        s  += v[i].x + v[i].y + v[i].z + v[i].w;
        ss += v[i].x*v[i].x + v[i].y*v[i].y + v[i].z*v[i].z + v[i].w*v[i].w;
    }
    #pragma unroll
    for (int o = 16; o > 0; o >>= 1) {
        s  += __shfl_xor_sync(0xffffffffu, s,  o);
        ss += __shfl_xor_sync(0xffffffffu, ss, o);
    }
    const float mu   = s * (1.0f / DM);
    const float var  = ss * (1.0f / DM) - mu*mu;
    const float rstd = rsqrtf(var + LN_EPS);

    const float4* G  = (const float4*)gamma;
    const float4* Bt = (const float4*)beta;
    uint2* Or = (uint2*)(out + (size_t)row*DM);
    #pragma unroll
    for (int i = 0; i < 8; i++) {
        const float4 g4 = G[lane + i*32];
        const float4 b4 = Bt[lane + i*32];
        uint2 st;
        st.x = pack_h2((v[i].x - mu)*rstd*g4.x + b4.x,
                       (v[i].y - mu)*rstd*g4.y + b4.y);
        st.y = pack_h2((v[i].z - mu)*rstd*g4.z + b4.z,
                       (v[i].w - mu)*rstd*g4.w + b4.w);
        Or[lane + i*32] = st;
    }
}

// ---------------------------------------------------------------------------
// Single prep kernel: z=0..5 -> transpose+round of Wq/Wk/Wv/Wo/W1/W2,
// bias concat folded into z=0 blocks 1024..1035. Grid (4096,1,6), block 256.
// ---------------------------------------------------------------------------
__global__ __launch_bounds__(256) void prep_kernel(
    const float* __restrict__ Wq, const float* __restrict__ Wk,
    const float* __restrict__ Wv, const float* __restrict__ Wo,
    const float* __restrict__ W1, const float* __restrict__ W2,
    __half* __restrict__ Tqkv, __half* __restrict__ To,
    __half* __restrict__ T1, __half* __restrict__ T2,
    const float* __restrict__ bq, const float* __restrict__ bk,
    const float* __restrict__ bv, float* __restrict__ bqkv)
{
    const int z = blockIdx.z;
    const float* W; __half* T; int K, N;
    switch (z) {
        case 0:  W = Wq; T = Tqkv;           K = DM;  N = DM;  break;
        case 1:  W = Wk; T = Tqkv + DM*DM;   K = DM;  N = DM;  break;
        case 2:  W = Wv; T = Tqkv + 2*DM*DM; K = DM;  N = DM;  break;
        case 3:  W = Wo; T = To;             K = DM;  N = DM;  break;
        case 4:  W = W1; T = T1;             K = DM;  N = DFF; break;
        default: W = W2; T = T2;             K = DFF; N = DM;  break;
    }
    // bias concat on z=0 blocks 1024..1035
    if (z == 0 && blockIdx.x >= 1024) {
        if (blockIdx.x < 1036) {
            const int i = (blockIdx.x - 1024)*256 + threadIdx.x;
            if (i < DM)        bqkv[i] = bq[i];
            else if (i < 2*DM) bqkv[i] = bk[i - DM];
            else               bqkv[i] = bv[i - 2*DM];
        }
        return;
    }
    const int nblk = N >> 5;
    const int bx = blockIdx.x % nblk, byk = blockIdx.x / nblk;
    if (byk >= (K >> 5)) return;

    __shared__ float tile[32][33];
    const int tx = threadIdx.x & 31, ty = threadIdx.x >> 5;
    const int n0 = bx*32, k0 = byk*32;
    #pragma unroll
    for (int i = ty; i < 32; i += 8)
        tile[i][tx] = W[(size_t)(k0 + i)*N + n0 + tx];
    __syncthreads();
    #pragma unroll
    for (int i = ty; i < 32; i += 8)
        T[(size_t)(n0 + i)*K + k0 + tx] = __float2half_rn(tile[tx][i]);
}

// ---------------------------------------------------------------------------
// fp16 mma.sync GEMM (R13/R15 proven form): C[M,N] = A[M,K] @ Bt[N,K]^T + bias
// 128x128 CTA tile, BK=64, 3-stage cp.async, 256 threads (8 warps, 2x4),
// warp tile 64x32, ldmatrix x4 fragments (A and B), 2 CTAs/SM.
// ---------------------------------------------------------------------------
#define GST    3
#define LDH    72
#define TILE_H (128*LDH)                 // halves per tile (9216)
#define STAGE_BYTES (2*TILE_H*2)         // A + B = 36864 B
#define GEMM_SMEM (GST*STAGE_BYTES)      // 110592 B

template<bool RELU, bool RES, bool HALF_OUT>
__global__ __launch_bounds__(256, 2) void mma_gemm(
    const __half* __restrict__ A, const __half* __restrict__ Bt,
    const float* __restrict__ bias, const float* __restrict__ res,
    void* __restrict__ Cv, int M, int N, int K)
{
    extern __shared__ char smc[];
    const uint32_t sm_b = smem_u32(smc);

    const int tid  = threadIdx.x;
    const int lane = tid & 31, wid = tid >> 5;
    const int wm = wid >> 2, wn = wid & 3;        // 2 x 4 warp grid
    const int gid = lane >> 2, tg = lane & 3;
    const int bx = blockIdx.x, by = blockIdx.y;

    const __half* Ab = A  + (size_t)by * 128 * K;
    const __half* Bb = Bt + (size_t)bx * 128 * K;
    const int nchunks = K >> 6;                   // K/64

    // ldmatrix per-lane offsets (bytes) within a stage's A / B tile
    const int la7    = lane & 7;
    const int colsel = ((lane >> 3) & 1) << 3;    // 0/8 (k half)
    const int rowsel = (lane >> 4) << 3;          // 0/8 (row group)
    uint32_t offA[4], offB4[2];
    {
        const int arow = la7 + ((lane >> 3) & 1) * 8;
        const int acol = (lane >> 4) * 8;
        #pragma unroll
        for (int mt = 0; mt < 4; mt++)
            offA[mt] = (uint32_t)(((wm*64 + mt*16 + arow)*LDH + acol) * 2);
        #pragma unroll
        for (int g = 0; g < 2; g++)
            offB4[g] = (uint32_t)(((wn*32 + g*16 + la7 + rowsel)*LDH + colsel) * 2);
    }

    // Stage loader: 2 tiles x 128 rows x 64 halves (8x16B per row)
    auto load_stage = [&](int st, int kt) {
        const uint32_t a_dst = sm_b + (uint32_t)st*STAGE_BYTES;
        const uint32_t b_dst = a_dst + TILE_H*2;
        const __half* as = Ab + (size_t)kt*64;
        const __half* bs = Bb + (size_t)kt*64;
        #pragma unroll
        for (int it = 0; it < 4; it++) {
            const int idx = it*256 + tid;
            const int r = idx >> 3, c8 = idx & 7;
            const uint32_t off = (uint32_t)(r*144 + c8*16);
            CP_ASYNC16(a_dst + off, as + (size_t)r*K + c8*8);
            CP_ASYNC16(b_dst + off, bs + (size_t)r*K + c8*8);
        }
        CP_COMMIT();
    };

    float acc[4][4][4];
    #pragma unroll
    for (int i = 0; i < 4; i++)
        #pragma unroll
        for (int j = 0; j < 4; j++)
            #pragma unroll
            for (int k = 0; k < 4; k++) acc[i][j][k] = 0.f;

    cudaGridDependencySynchronize();

    load_stage(0, 0);
    if (nchunks > 1) load_stage(1, 1);

    for (int i = 0; i < nchunks; i++) {
        const int st = i % GST;
        if (i + 1 < nchunks) { CP_WAIT(1); } else { CP_WAIT(0); }
        __syncthreads();

        if (i + (GST-1) < nchunks)
            load_stage((i + GST - 1) % GST, i + GST - 1);

        const uint32_t aBase = sm_b + (uint32_t)st*STAGE_BYTES;
        const uint32_t bBase = aBase + TILE_H*2;

        #pragma unroll
        for (int kk = 0; kk < 4; kk++) {
            uint32_t a[4][4], b[2][4];
            #pragma unroll
            for (int mt = 0; mt < 4; mt++)
                LDSM_X4(a[mt][0], a[mt][1], a[mt][2], a[mt][3],
                        aBase + offA[mt] + kk*32);
            #pragma unroll
            for (int g = 0; g < 2; g++)
                LDSM_X4(b[g][0], b[g][1], b[g][2], b[g][3],
                        bBase + offB4[g] + kk*32);
            #pragma unroll
            for (int mt = 0; mt < 4; mt++) {
                #pragma unroll
                for (int g = 0; g < 2; g++) {
                    MMA_F16(acc[mt][2*g],   a[mt], b[g][0], b[g][1]);
                    MMA_F16(acc[mt][2*g+1], a[mt], b[g][2], b[g][3]);
                }
            }
        }
        // no trailing barrier: next iteration's top sync protects stage reuse
    }

    // Epilogue
    #pragma unroll
    for (int mt = 0; mt < 4; mt++) {
        #pragma unroll
        for (int nt = 0; nt < 4; nt++) {
            const int r0 = by*128 + wm*64 + mt*16 + gid;
            const int c  = bx*128 + wn*32 + nt*8 + tg*2;
            const float2 b2 = *(const float2*)(bias + c);
            #pragma unroll
            for (int half_i = 0; half_i < 2; half_i++) {
                const int r = r0 + half_i*8;
                float ox = acc[mt][nt][half_i*2+0] + b2.x;
                float oy = acc[mt][nt][half_i*2+1] + b2.y;
                if (RELU) { ox = fmaxf(ox, 0.f); oy = fmaxf(oy, 0.f); }
                if (RES) {
                    const float2 r2 = *(const float2*)(res + (size_t)r*N + c);
                    ox += r2.x; oy += r2.y;
                }
                if (HALF_OUT) {
                    *(uint32_t*)((__half*)Cv + (size_t)r*N + c) = pack_h2(ox, oy);
                } else {
                    float2 o; o.x = ox; o.y = oy;
                    *(float2*)((float*)Cv + (size_t)r*N + c) = o;
                }
            }
        }
    }
}

// ---------------------------------------------------------------------------
// fp16 tensor-core causal flash attention, d_k=64, fused QKV input.
// CTA: 256 threads (8 warps), 128 q rows (16/warp), 64-key KV tiles.
// 6-stage cp.async ring, TWO tiles processed per barrier (n_kt always even),
// K frags via ldmatrix.x4, warp-level skip of fully masked tiles, softmax
// row-sum l via ones-column MMA, exp+pack fused into PV, S zero-init via
// the MMA C operand (no per-tile register clears).
// ---------------------------------------------------------------------------
#define ALDH 72
#define ATILE_B (64*ALDH*2)               // 9216 B per 64x64 half tile
#define ASTAGES 6
#define ATT_SMEM (2*ASTAGES*ATILE_B)      // 6 stages x (K+V) = 110592 B
#define FA_C1 0.1803368801111204f          // log2(e)/8
#define ONES_H2 0x3C003C00u                // half2(1.0, 1.0)

__global__ __launch_bounds__(256, 2) void fa_kernel(
    const __half* __restrict__ QKV, __half* __restrict__ O)
{
    extern __shared__ char fsc[];
    const int tid  = threadIdx.x;
    const int lane = tid & 31, w = tid >> 5;      // 8 warps
    const int gid  = lane >> 2, tg = lane & 3;
    const int qt   = (int)gridDim.x - 1 - (int)blockIdx.x;   // big tiles first
    const int bh   = blockIdx.y;
    const int b    = bh >> 4, h = bh & 15;
    const int qbase = qt * 128;
    const int n_kt  = 2*qt + 2;                   // even, >= 2

    const uint32_t fs_b = smem_u32(fsc);

    // 64-row tile loader (256 threads, 2 chunks each)
    auto load_tile = [&](uint32_t d0, const __half* src) {
        #pragma unroll
        for (int i = 0; i < 2; i++) {
            const int idx = i*256 + tid;
            const int r = idx >> 3, c8 = idx & 7;
            CP_ASYNC16(d0 + (uint32_t)(r*144 + c8*16), src + (size_t)r*QKVS + c8*8);
        }
    };

    const __half* Kg = QKV + (size_t)(b*SS)*QKVS + DM + h*DK;
    const __half* Vg = QKV + (size_t)(b*SS)*QKVS + 2*DM + h*DK;
    auto load_kv = [&](int st, int kt) {
        load_tile(fs_b + (uint32_t)st*(2*ATILE_B),           Kg + (size_t)(kt*64)*QKVS);
        load_tile(fs_b + (uint32_t)st*(2*ATILE_B) + ATILE_B, Vg + (size_t)(kt*64)*QKVS);
        CP_COMMIT();
    };

    // ldmatrix per-lane offsets
    const int la7    = lane & 7;
    const int colsel = ((lane >> 3) & 1) << 3;    // 0/8 (k half)
    const int rowsel = (lane >> 4) << 3;          // 0/8 (row pair group)
    const uint32_t offQ = (uint32_t)(((w*16 + la7 + ((lane>>3)&1)*8)*ALDH
                                     + (lane>>4)*8) * 2);
    uint32_t offK4[4];
    #pragma unroll
    for (int g = 0; g < 4; g++)
        offK4[g] = (uint32_t)(((g*16 + la7 + rowsel)*ALDH + colsel) * 2);

    cudaGridDependencySynchronize();

    // --- Stage 128-row Q tile through smem (stage 0+1 region) ---
    {
        const __half* qsrc = QKV + (size_t)(b*SS + qbase)*QKVS + h*DK;
        #pragma unroll
        for (int i = 0; i < 4; i++) {
            const int idx = i*256 + tid;
            const int r = idx >> 3, c8 = idx & 7;
            CP_ASYNC16(fs_b + (uint32_t)(r*144 + c8*16), qsrc + (size_t)r*QKVS + c8*8);
        }
        CP_COMMIT();
        CP_WAIT(0);
    }
    __syncthreads();

    uint32_t qf[4][4];
    #pragma unroll
    for (int kk = 0; kk < 4; kk++)
        LDSM_X4(qf[kk][0], qf[kk][1], qf[kk][2], qf[kk][3],
                fs_b + offQ + kk*32);
    __syncthreads();

    // Prologue: fill up to 4 stages
    load_kv(0, 0);
    load_kv(1, 1);
    if (n_kt > 2) load_kv(2, 2);
    if (n_kt > 3) load_kv(3, 3);

    float oacc[8][4];
    #pragma unroll
    for (int d = 0; d < 8; d++) {
        oacc[d][0] = 0.f; oacc[d][1] = 0.f; oacc[d][2] = 0.f; oacc[d][3] = 0.f;
    }
    float lacc[4] = {0.f, 0.f, 0.f, 0.f};         // ones-MMA row sums
    float m0r = -INFINITY, m1r = -INFINITY;
    const float fz = 0.0f;
    const int lm = lane >> 3, lr = lane & 7;

    // Process one 64-key tile from stage base sb
    auto process = [&](uint32_t sb, int t) {
        if (t == n_kt - 1 && w < 4) return;       // fully masked for warps 0-3
        const uint32_t ks_b = sb;
        const uint32_t vs_b = sb + ATILE_B;

        // ---- S = Q K^T (zero-init via MMA C operand on kk=0) ----
        float sacc[8][4];
        #pragma unroll
        for (int g = 0; g < 4; g++) {
            uint32_t b0, b1, b2, b3;
            LDSM_X4(b0, b1, b2, b3, ks_b + offK4[g]);
            MMA_F16_Z(sacc[2*g],   qf[0], b0, b1, fz);
            MMA_F16_Z(sacc[2*g+1], qf[0], b2, b3, fz);
        }
        #pragma unroll
        for (int kk = 1; kk < 4; kk++) {
            #pragma unroll
            for (int g = 0; g < 4; g++) {
                uint32_t b0, b1, b2, b3;
                LDSM_X4(b0, b1, b2, b3, ks_b + offK4[g] + kk*32);
                MMA_F16(sacc[2*g],   qf[kk], b0, b1);
                MMA_F16(sacc[2*g+1], qf[kk], b2, b3);
            }
        }

        // ---- causal mask (only where it can bite) ----
        if (t == n_kt - 1 || (t == n_kt - 2 && w < 4)) {
            const int koff = t*64 - qbase;        // 0 or 64
            const int q0 = w*16 + gid;
            #pragma unroll
            for (int nt = 0; nt < 8; nt++) {
                const int s0 = koff + nt*8 + 2*tg;
                if (s0     > q0)     sacc[nt][0] = -1e30f;
                if (s0 + 1 > q0)     sacc[nt][1] = -1e30f;
                if (s0     > q0 + 8) sacc[nt][2] = -1e30f;
                if (s0 + 1 > q0 + 8) sacc[nt][3] = -1e30f;
            }
        }

        // ---- online softmax in exp2 domain ----
        float t0 = -1e30f, t1 = -1e30f;
        #pragma unroll
        for (int nt = 0; nt < 8; nt++) {
            t0 = fmaxf(t0, fmaxf(sacc[nt][0], sacc[nt][1]));
            t1 = fmaxf(t1, fmaxf(sacc[nt][2], sacc[nt][3]));
        }
        t0 = fmaxf(t0, __shfl_xor_sync(0xffffffffu, t0, 1));
        t0 = fmaxf(t0, __shfl_xor_sync(0xffffffffu, t0, 2));
        t1 = fmaxf(t1, __shfl_xor_sync(0xffffffffu, t1, 1));
        t1 = fmaxf(t1, __shfl_xor_sync(0xffffffffu, t1, 2));

        const float mn0 = fmaxf(m0r, t0), mn1 = fmaxf(m1r, t1);
        const bool chg = (mn0 > m0r) || (mn1 > m1r);
        if (__any_sync(0xffffffffu, chg)) {
            const float cr0 = ex2((m0r - mn0) * FA_C1);
            const float cr1 = ex2((m1r - mn1) * FA_C1);
            lacc[0] *= cr0; lacc[1] *= cr0; lacc[2] *= cr1; lacc[3] *= cr1;
            #pragma unroll
            for (int d = 0; d < 8; d++) {
                oacc[d][0] *= cr0; oacc[d][1] *= cr0;
                oacc[d][2] *= cr1; oacc[d][3] *= cr1;
            }
        }
        m0r = mn0; m1r = mn1;

        // ---- exp + pack + (l via ones-MMA) + O += P V, fused ----
        const float mc0 = mn0 * FA_C1, mc1 = mn1 * FA_C1;
        #pragma unroll
        for (int j = 0; j < 4; j++) {
            uint32_t a[4];
            {
                const float p00 = ex2(fmaf(sacc[2*j  ][0], FA_C1, -mc0));
                const float p01 = ex2(fmaf(sacc[2*j  ][1], FA_C1, -mc0));
                const float p02 = ex2(fmaf(sacc[2*j  ][2], FA_C1, -mc1));
                const float p03 = ex2(fmaf(sacc[2*j  ][3], FA_C1, -mc1));
                const float p10 = ex2(fmaf(sacc[2*j+1][0], FA_C1, -mc0));
                const float p11 = ex2(fmaf(sacc[2*j+1][1], FA_C1, -mc0));
                const float p12 = ex2(fmaf(sacc[2*j+1][2], FA_C1, -mc1));
                const float p13 = ex2(fmaf(sacc[2*j+1][3], FA_C1, -mc1));
                a[0] = pack_h2(p00, p01);
                a[1] = pack_h2(p02, p03);
                a[2] = pack_h2(p10, p11);
                a[3] = pack_h2(p12, p13);
            }
            MMA_F16(lacc, a, ONES_H2, ONES_H2);   // row sums -> lacc
            #pragma unroll
            for (int dtp = 0; dtp < 4; dtp++) {
                const int s_a = j*16 + ((lm & 1) << 3) + lr;
                const int d_a = dtp*16 + ((lm >> 1) << 3);
                const uint32_t addr = vs_b + (uint32_t)(s_a*ALDH + d_a)*2;
                uint32_t b0, b1, b2, b3;
                LDSM_X4_TRANS(b0, b1, b2, b3, addr);
                MMA_F16(oacc[dtp*2],   a, b0, b1);
                MMA_F16(oacc[dtp*2+1], a, b2, b3);
            }
        }
    };

    // Main loop: two tiles per barrier (n_kt even)
    int pf = 4, pfs = 4;                           // next tile to prefetch + its stage
    int s0i = 0;                                   // stage of tile kt
    for (int kt = 0; kt < n_kt; kt += 2) {
        if (kt + 2 < n_kt) { CP_WAIT(2); } else { CP_WAIT(0); }
        __syncthreads();

        if (pf < n_kt) { load_kv(pfs, pf); pf++; if (++pfs == ASTAGES) pfs = 0; }
        if (pf < n_kt) { load_kv(pfs, pf); pf++; if (++pfs == ASTAGES) pfs = 0; }

        const int s1i = (s0i + 1 == ASTAGES) ? 0 : s0i + 1;
        process(fs_b + (uint32_t)s0i*(2*ATILE_B), kt);
        process(fs_b + (uint32_t)s1i*(2*ATILE_B), kt + 1);
        s0i = (s1i + 1 == ASTAGES) ? 0 : s1i + 1;
        // no trailing barrier: next iteration's top sync protects stage reuse
    }

    // ---- normalize + write (fp16; feeds Wo GEMM) ----
    const float inv0 = 1.0f / lacc[0], inv1 = 1.0f / lacc[2];
    const int r0 = b*SS + qbase + w*16 + gid;
    __half* o0 = O + (size_t)r0*DM + h*DK;
    __half* o1 = o0 + (size_t)8*DM;
    #pragma unroll
    for (int dt = 0; dt < 8; dt++) {
        const int c = dt*8 + 2*tg;
        *(uint32_t*)(o0 + c) = pack_h2(oacc[dt][0]*inv0, oacc[dt][1]*inv0);
        *(uint32_t*)(o1 + c) = pack_h2(oacc[dt][2]*inv1, oacc[dt][3]*inv1);
    }
}

// ---------------------------------------------------------------------------
// PDL launch helper: ProgrammaticStreamSerialization on dependent launches
// ---------------------------------------------------------------------------
template<typename F, typename... Args>
static inline void pdl_launch(F* f, dim3 g, dim3 b, size_t smem, Args... args) {
    cudaLaunchConfig_t cfg = {};
    cfg.gridDim = g; cfg.blockDim = b; cfg.dynamicSmemBytes = smem;
    cfg.stream = 0;
    cudaLaunchAttribute at[1];
    at[0].id = cudaLaunchAttributeProgrammaticStreamSerialization;
    at[0].val.programmaticStreamSerializationAllowed = 1;
    cfg.attrs = at; cfg.numAttrs = 1;
    cudaLaunchKernelEx(&cfg, f, args...);
}

// ---------------------------------------------------------------------------
// Launch
// ---------------------------------------------------------------------------
extern "C" void kernel_launch(void* const* d_in, const int* in_sizes, int n_in,
                              void* d_out, int out_size)
{
    const float* x   = (const float*)d_in[0];
    const float* Wq  = (const float*)d_in[1];
    const float* bq  = (const float*)d_in[2];
    const float* Wk  = (const float*)d_in[3];
    const float* bk  = (const float*)d_in[4];
    const float* Wv  = (const float*)d_in[5];
    const float* bv  = (const float*)d_in[6];
    const float* Wo  = (const float*)d_in[7];
    const float* bo  = (const float*)d_in[8];
    const float* W1  = (const float*)d_in[9];
    const float* b1  = (const float*)d_in[10];
    const float* W2  = (const float*)d_in[11];
    const float* b2  = (const float*)d_in[12];
    const float* g1  = (const float*)d_in[13];
    const float* be1 = (const float*)d_in[14];
    const float* g2  = (const float*)d_in[15];
    const float* be2 = (const float*)d_in[16];
    float* out = (float*)d_out;

    __half *p_h, *p_qkv, *p_o, *p_ff;
    __half *p_wqkvt, *p_wot, *p_w1t, *p_w2t;
    float  *p_x1, *p_bqkv;
    cudaGetSymbolAddress((void**)&p_h,     g_h);
    cudaGetSymbolAddress((void**)&p_qkv,   g_qkv);
    cudaGetSymbolAddress((void**)&p_o,     g_o);
    cudaGetSymbolAddress((void**)&p_x1,    g_x1);
    cudaGetSymbolAddress((void**)&p_ff,    g_ff);
    cudaGetSymbolAddress((void**)&p_wqkvt, g_wqkvt);
    cudaGetSymbolAddress((void**)&p_wot,   g_wot);
    cudaGetSymbolAddress((void**)&p_w1t,   g_w1t);
    cudaGetSymbolAddress((void**)&p_w2t,   g_w2t);
    cudaGetSymbolAddress((void**)&p_bqkv,  g_bqkv);

    static bool attr_set = false;
    if (!attr_set) {
        cudaFuncSetAttribute(mma_gemm<false,false,true>,
                             cudaFuncAttributeMaxDynamicSharedMemorySize, GEMM_SMEM);
        cudaFuncSetAttribute(mma_gemm<false,true,false>,
                             cudaFuncAttributeMaxDynamicSharedMemorySize, GEMM_SMEM);
        cudaFuncSetAttribute(mma_gemm<true,false,true>,
                             cudaFuncAttributeMaxDynamicSharedMemorySize, GEMM_SMEM);
        cudaFuncSetAttribute(fa_kernel,
                             cudaFuncAttributeMaxDynamicSharedMemorySize, ATT_SMEM);
        attr_set = true;
    }

    // 0. single prep launch: all transposes + bias concat
    prep_kernel<<<dim3(4096, 1, 6), 256>>>(
        Wq, Wk, Wv, Wo, W1, W2,
        p_wqkvt, p_wot, p_w1t, p_w2t, bq, bk, bv, p_bqkv);

    const dim3 gQKV(QKVS/128, MROWS/128);  // (24, 64)
    const dim3 gD  (DM/128,   MROWS/128);  // (8, 64)
    const dim3 gF  (DFF/128,  MROWS/128);  // (32, 64)
    const dim3 blk(256);

    // 1. ln1(x) -> h (fp16)
    pdl_launch(&ln_kernel, dim3(MROWS/8), blk, 0, x, g1, be1, p_h);
    // 2. fused QKV projection (fp16 tensor pipe, N=3072)
    pdl_launch(&mma_gemm<false,false,true>, gQKV, blk, (size_t)GEMM_SMEM,
               (const __half*)p_h, (const __half*)p_wqkvt, (const float*)p_bqkv,
               (const float*)nullptr, (void*)p_qkv, MROWS, QKVS, DM);
    // 3. causal attention (fp16 flash attention, 128-row q tiles)
    pdl_launch(&fa_kernel, dim3(SS/128, BB*HH), blk, (size_t)ATT_SMEM,
               (const __half*)p_qkv, p_o);
    // 4. output projection + residual(x) -> x1 (fp32)
    pdl_launch(&mma_gemm<false,true,false>, gD, blk, (size_t)GEMM_SMEM,
               (const __half*)p_o, (const __half*)p_wot, bo,
               x, (void*)p_x1, MROWS, DM, DM);
    // 5. ln2(x1) -> h (fp16)
    pdl_launch(&ln_kernel, dim3(MROWS/8), blk, 0,
               (const float*)p_x1, g2, be2, p_h);
    // 6. FFN up + ReLU (fp16 out)
    pdl_launch(&mma_gemm<true,false,true>, gF, blk, (size_t)GEMM_SMEM,
               (const __half*)p_h, (const __half*)p_w1t, b1,
               (const float*)nullptr, (void*)p_ff, MROWS, DFF, DM);
    // 7. FFN down + residual(x1) -> out (fp32)
    pdl_launch(&mma_gemm<false,true,false>, gD, blk, (size_t)GEMM_SMEM,
               (const __half*)p_ff, (const __half*)p_w2t, b2,
               (const float*)p_x1, (void*)out, MROWS, DM, DFF);
}